// round 10
// baseline (speedup 1.0000x reference)
#include <cuda_runtime.h>

// Balanced-softmax loss:
// loss = -(1/B) * sum_b [ pred[b,t] + log(freq[t]) - log( sum_c exp(pred[b,c])*freq[c] ) ]
// pred: [32768, 1000] fp32, target: [32768] int32 OR int64 (runtime-probed),
// out: 1 fp32 scalar.

#define NCLASS 1000
#define NROWS  32768
#define WARPS_PER_BLOCK 8
#define THREADS (WARPS_PER_BLOCK * 32)
#define NVEC 250  // 1000 / 4 float4 per row

__device__ float  g_freq[NCLASS];
__device__ double g_acc;
__device__ int    g_is64;   // 1 if target is int64 (little-endian), else 0

__device__ __forceinline__ int clamp_class(int t) {
    t = t < 0 ? 0 : t;
    return t >= NCLASS ? NCLASS - 1 : t;
}

__device__ __forceinline__ int load_label(const int* __restrict__ t32, int i, int is64) {
    return clamp_class(is64 ? t32[2 * i] : t32[i]);
}

__global__ void zero_kernel(const int* __restrict__ t32) {
    int i = blockIdx.x * blockDim.x + threadIdx.x;
    if (i < NCLASS) g_freq[i] = 0.0f;
    if (i == 0) {
        g_acc = 0.0;
        // Dtype probe: int64 labels < 1000 have zero high words at odd int32
        // indices. Reads 512 B — in-bounds under either layout.
        int is64 = 1;
        #pragma unroll 8
        for (int k = 0; k < 64; k++) {
            if (t32[2 * k + 1] != 0) { is64 = 0; break; }
        }
        g_is64 = is64;
    }
}

__global__ void hist_kernel(const int* __restrict__ t32, int n) {
    int is64 = g_is64;
    for (int i = blockIdx.x * blockDim.x + threadIdx.x; i < n;
         i += gridDim.x * blockDim.x) {
        atomicAdd(&g_freq[load_label(t32, i, is64)], 1.0f);
    }
}

__global__ __launch_bounds__(THREADS) void main_kernel(
    const float* __restrict__ pred,
    const int* __restrict__ t32)
{
    __shared__ float4 s_freq[NVEC];
    __shared__ double s_part[WARPS_PER_BLOCK];

    int tid = threadIdx.x;
    for (int i = tid; i < NVEC; i += THREADS) {
        s_freq[i] = reinterpret_cast<const float4*>(g_freq)[i];
    }
    __syncthreads();

    int warp = tid >> 5;
    int lane = tid & 31;
    int row  = blockIdx.x * WARPS_PER_BLOCK + warp;

    const float4* p = reinterpret_cast<const float4*>(pred + (size_t)row * NCLASS);

    // Hoisted label + picked-logit loads: DRAM latency hides under the
    // streaming loop rather than the post-reduction tail.
    int   t  = (lane == 0) ? load_label(t32, row, g_is64) : 0;
    float pt = (lane == 0) ? __ldg(pred + (size_t)row * NCLASS + t) : 0.0f;

    // 4 independent accumulators: no serialized FFMA chain; MUFU overlaps
    // the LDG stream.
    float s0 = 0.0f, s1 = 0.0f, s2 = 0.0f, s3 = 0.0f;
    #pragma unroll 8
    for (int i = lane; i < NVEC; i += 32) {
        float4 v = p[i];          // coalesced 128B/warp segments
        float4 f = s_freq[i];
        s0 += __expf(v.x) * f.x;
        s1 += __expf(v.y) * f.y;
        s2 += __expf(v.z) * f.z;
        s3 += __expf(v.w) * f.w;
    }
    float sum = (s0 + s1) + (s2 + s3);

    #pragma unroll
    for (int o = 16; o > 0; o >>= 1)
        sum += __shfl_xor_sync(0xffffffffu, sum, o);

    if (lane == 0) {
        float ft = reinterpret_cast<const float*>(s_freq)[t];
        float term = pt + __logf(ft) - __logf(sum);
        s_part[warp] = (double)term;
    }
    __syncthreads();

    if (tid == 0) {
        double d = 0.0;
        #pragma unroll
        for (int w = 0; w < WARPS_PER_BLOCK; w++) d += s_part[w];
        atomicAdd(&g_acc, d);   // 4096 atomics total — negligible
    }
}

__global__ void final_kernel(float* out) {
    out[0] = (float)(-g_acc / (double)NROWS);
}

extern "C" void kernel_launch(void* const* d_in, const int* in_sizes, int n_in,
                              void* d_out, int out_size) {
    const float* pred = (const float*)d_in[0];
    const int*   t32  = (const int*)d_in[1];
    float*       out  = (float*)d_out;

    zero_kernel<<<1, 1024>>>(t32);
    hist_kernel<<<128, 256>>>(t32, NROWS);
    main_kernel<<<NROWS / WARPS_PER_BLOCK, THREADS>>>(pred, t32);
    final_kernel<<<1, 1>>>(out);
}